// round 16
// baseline (speedup 1.0000x reference)
#include <cuda_runtime.h>
#include <cuda_fp16.h>
#include <math.h>

#define BDIM 8
#define UDIM 16384
#define SDIM 4096           // 64*64
#define EDIM 128
#define NH   8
#define BU (BDIM*UDIM)      // 131072
#define BS (BDIM*SDIM)      // 32768
#define CAP 48              // max tokens per bucket (Poisson(4); max ~18 across 32k buckets)

typedef unsigned long long u64;
__device__ __forceinline__ u64 pack2(float a, float b) {
    u64 r; asm("mov.b64 %0,{%1,%2};" : "=l"(r) : "f"(a), "f"(b)); return r;
}
__device__ __forceinline__ void unpack2(float& a, float& b, u64 v) {
    asm("mov.b64 {%0,%1},%2;" : "=f"(a), "=f"(b) : "l"(v));
}
__device__ __forceinline__ u64 fma2(u64 a, u64 b, u64 c) {
    u64 d; asm("fma.rn.f32x2 %0,%1,%2,%3;" : "=l"(d) : "l"(a), "l"(b), "l"(c)); return d;
}

// -------- scratch (device globals; no cudaMalloc allowed) --------
__device__ __align__(16) int g_bcount[BS];
__device__ __align__(16) int g_btab[(size_t)BS*CAP];
__device__ float  g_A[(size_t)SDIM*NH*EDIM];             // 16MB score projectors
__device__ __align__(16) __half g_vaccH[(size_t)BS*NH*EDIM];  // 67MB fp16 vacc
__device__ float  g_hidden[(size_t)BS*EDIM];             // 16MB

// ============ fused bucketize + direct scatter ============
__global__ void scatter_direct_kernel(const float* __restrict__ xc_off) {
    int i = blockIdx.x*blockDim.x + threadIdx.x;
    if (i >= BU) return;
    float2 xy = ((const float2*)xc_off)[i];
    const float sp   = 1.0f / 63.0f;
    const float half = sp * 0.5f;
    float nx = floorf((xy.x + half) / sp);
    float ny = floorf((xy.y + half) / sp);
    nx = fminf(fmaxf(nx, 0.0f), 63.0f);
    ny = fminf(fmaxf(ny, 0.0f), 63.0f);
    int b   = i / UDIM;
    int seg = b*SDIM + (int)nx * 64 + (int)ny;
    int pos = atomicAdd(&g_bcount[seg], 1);
    if (pos < CAP) g_btab[(size_t)seg*CAP + pos] = i;
}

// ============ fused Q-GEMM + A-projector ============
#define QTILE 32
__global__ void qaproj_kernel(const float* __restrict__ latents,
                              const float* __restrict__ Wq,
                              const float* __restrict__ Wk)
{
    extern __shared__ float smem[];
    float* sWq  = smem;                          // 128*128
    float* sLat = smem + EDIM*EDIM;              // 32*128
    float* sQ   = sLat + QTILE*EDIM;             // 32*128
    int tid = threadIdx.x;
    int s0 = blockIdx.x * QTILE;

    for (int i = tid; i < EDIM*EDIM/4; i += 256)
        ((float4*)sWq)[i] = ((const float4*)Wq)[i];
    for (int i = tid; i < QTILE*32; i += 256)
        ((float4*)sLat)[i] = ((const float4*)latents)[(size_t)s0*32 + i];
    __syncthreads();

    // phase 2: q rows (register-blocked, f32x2)
    {
        int rg = tid >> 5;
        int c  = tid & 31;
        const ulonglong2* sW2 = (const ulonglong2*)sWq;
        u64 acc01[4], acc23[4];
        #pragma unroll
        for (int j = 0; j < 4; j++) { acc01[j] = pack2(0.f,0.f); acc23[j] = pack2(0.f,0.f); }
        const float* aB = sLat + (rg << 2) * EDIM;
        #pragma unroll 1
        for (int k4 = 0; k4 < EDIM/4; k4++) {
            float4 a4[4];
            #pragma unroll
            for (int j = 0; j < 4; j++)
                a4[j] = *(const float4*)(aB + j*EDIM + k4*4);
            #pragma unroll
            for (int kk = 0; kk < 4; kk++) {
                ulonglong2 wp = sW2[(k4*4 + kk)*32 + c];
                #pragma unroll
                for (int j = 0; j < 4; j++) {
                    float av = ((const float*)&a4[j])[kk];
                    u64 ap = pack2(av, av);
                    acc01[j] = fma2(ap, wp.x, acc01[j]);
                    acc23[j] = fma2(ap, wp.y, acc23[j]);
                }
            }
        }
        #pragma unroll
        for (int j = 0; j < 4; j++) {
            float4 o;
            unpack2(o.x, o.y, acc01[j]);
            unpack2(o.z, o.w, acc23[j]);
            o.x *= 0.25f; o.y *= 0.25f; o.z *= 0.25f; o.w *= 0.25f;
            ((float4*)sQ)[((rg << 2) + j)*32 + c] = o;
        }
    }
    __syncthreads();

    // phase 3: aproj
    {
        int h = tid >> 5;
        int lane = tid & 31;
        const float4* Wk4 = (const float4*)Wk;
        const float4* sq4 = (const float4*)sQ;

        float4 w[4][4];
        #pragma unroll
        for (int j = 0; j < 4; j++)
            #pragma unroll
            for (int d4 = 0; d4 < 4; d4++)
                w[j][d4] = Wk4[(size_t)(4*lane + j)*32 + 4*h + d4];

        for (int s = 0; s < QTILE; s++) {
            float4 qf[4];
            #pragma unroll
            for (int d4 = 0; d4 < 4; d4++) qf[d4] = sq4[s*32 + 4*h + d4];
            float o[4];
            #pragma unroll
            for (int j = 0; j < 4; j++) {
                float acc = 0.f;
                #pragma unroll
                for (int d4 = 0; d4 < 4; d4++) {
                    acc += w[j][d4].x*qf[d4].x + w[j][d4].y*qf[d4].y
                         + w[j][d4].z*qf[d4].z + w[j][d4].w*qf[d4].w;
                }
                o[j] = acc;
            }
            ((float4*)g_A)[(size_t)(s0 + s)*NH*32 + h*32 + lane] =
                make_float4(o[0], o[1], o[2], o[3]);
        }
    }
}

// ============ GEMM (register-blocked, f32x2, 4-k chunks) ============
__global__ void gemm_kernel(const float* __restrict__ A0,
                            const float* __restrict__ W,
                            float* __restrict__ C,
                            float scale, int Mtotal)
{
    extern __shared__ float smem[];
    float* sW = smem;              // 128*128
    float* sA = smem + EDIM*EDIM;  // 64*128
    int tid = threadIdx.x;

    for (int i = tid; i < EDIM*EDIM/4; i += 256)
        ((float4*)sW)[i] = ((const float4*)W)[i];

    int rg = tid >> 5;
    int c  = tid & 31;
    const ulonglong2* sW2 = (const ulonglong2*)sW;
    int nTiles = (Mtotal + 63) >> 6;

    for (int tile = blockIdx.x; tile < nTiles; tile += gridDim.x) {
        int base = tile << 6;
        __syncthreads();
        for (int i = tid; i < 64*32; i += 256) {
            int gr = base + (i >> 5);
            if (gr < Mtotal)
                ((float4*)sA)[i] = ((const float4*)A0)[(size_t)gr*32 + (i & 31)];
        }
        __syncthreads();

        u64 acc01[8], acc23[8];
        #pragma unroll
        for (int j = 0; j < 8; j++) { acc01[j] = pack2(0.f, 0.f); acc23[j] = pack2(0.f, 0.f); }

        const float* aB = sA + (rg << 3) * EDIM;
        #pragma unroll 1
        for (int k4 = 0; k4 < EDIM/4; k4++) {
            float4 a4[8];
            #pragma unroll
            for (int j = 0; j < 8; j++)
                a4[j] = *(const float4*)(aB + j*EDIM + k4*4);
            #pragma unroll
            for (int kk = 0; kk < 4; kk++) {
                ulonglong2 wp = sW2[(k4*4 + kk)*32 + c];
                #pragma unroll
                for (int j = 0; j < 8; j++) {
                    float av = ((const float*)&a4[j])[kk];
                    u64 ap = pack2(av, av);
                    acc01[j] = fma2(ap, wp.x, acc01[j]);
                    acc23[j] = fma2(ap, wp.y, acc23[j]);
                }
            }
        }
        #pragma unroll
        for (int j = 0; j < 8; j++) {
            int gr = base + (rg << 3) + j;
            if (gr < Mtotal) {
                float4 o;
                unpack2(o.x, o.y, acc01[j]);
                unpack2(o.z, o.w, acc23[j]);
                o.x *= scale; o.y *= scale; o.z *= scale; o.w *= scale;
                ((float4*)C)[(size_t)gr*32 + c] = o;
            }
        }
    }
}

// ============ attention: warp/bucket, direct-exp softmax, batched, fp16 vacc out ============
__global__ __launch_bounds__(128) void attn_kernel(
    const float* __restrict__ zc_off,
    const float* __restrict__ zc_on,
    const float* __restrict__ fake,
    const int*   __restrict__ ignore_flag,
    int w_base)
{
    int w    = w_base + ((blockIdx.x*blockDim.x + threadIdx.x) >> 5);
    int lane = threadIdx.x & 31;
    int s = w & (SDIM - 1);

    const float4* A4 = (const float4*)g_A;
    float4 areg[NH];
    #pragma unroll
    for (int h = 0; h < NH; h++)
        areg[h] = A4[(size_t)s*NH*32 + h*32 + lane];

    int cnt = g_bcount[w];
    if (cnt > CAP) cnt = CAP;
    const int* tp = g_btab + (size_t)w*CAP;
    const float* lastz = (*ignore_flag != 0) ? fake : (zc_on + (size_t)w*EDIM);

    float l[NH];
    u64 acc01[NH], acc23[NH];
    #pragma unroll
    for (int h = 0; h < NH; h++) {
        l[h] = 0.f; acc01[h] = pack2(0.f,0.f); acc23[h] = pack2(0.f,0.f);
    }

    for (int i = 0; i <= cnt; i += 4) {
        float4 z[4];
        #pragma unroll
        for (int t = 0; t < 4; t++) {
            int j = i + t;
            const float* zp = (j < cnt) ? (zc_off + (size_t)tp[j]*EDIM) : lastz;
            z[t] = ((const float4*)zp)[lane];
        }

        float v[32];
        #pragma unroll
        for (int t = 0; t < 4; t++)
            #pragma unroll
            for (int h = 0; h < NH; h++)
                v[t*8+h] = z[t].x*areg[h].x + z[t].y*areg[h].y
                         + z[t].z*areg[h].z + z[t].w*areg[h].w;

        #pragma unroll
        for (int o = 16; o >= 1; o >>= 1) {
            bool up = (lane & o) != 0;
            #pragma unroll
            for (int j = 0; j < o; j++) {
                float sendv = up ? v[j] : v[j+o];
                float got = __shfl_xor_sync(0xffffffffu, sendv, o);
                v[j] = (up ? v[j+o] : v[j]) + got;
            }
        }
        float pown = __expf(v[0]);

        u64 zp01[4], zp23[4];
        #pragma unroll
        for (int t = 0; t < 4; t++) {
            zp01[t] = pack2(z[t].x, z[t].y);
            zp23[t] = pack2(z[t].z, z[t].w);
        }
        #pragma unroll
        for (int t = 0; t < 4; t++) {
            if (i + t <= cnt) {
                #pragma unroll
                for (int h = 0; h < NH; h++) {
                    float p = __shfl_sync(0xffffffffu, pown, t*8 + h);
                    u64 pp = pack2(p, p);
                    l[h] += p;
                    acc01[h] = fma2(pp, zp01[t], acc01[h]);
                    acc23[h] = fma2(pp, zp23[t], acc23[h]);
                }
            }
        }
    }

    #pragma unroll
    for (int h = 0; h < NH; h++) {
        float inv = 1.0f / l[h];
        float4 o;
        unpack2(o.x, o.y, acc01[h]);
        unpack2(o.z, o.w, acc23[h]);
        __half2 p01 = __floats2half2_rn(o.x*inv, o.y*inv);
        __half2 p23 = __floats2half2_rn(o.z*inv, o.w*inv);
        uint2 u;
        u.x = *(unsigned*)&p01;
        u.y = *(unsigned*)&p23;
        *(uint2*)(g_vaccH + (size_t)w*NH*EDIM + h*EDIM + 4*lane) = u;
    }
}

// ============ vfold (persistent, 8 rows/tile, 2 blocks/SM) ============
// hidden[n][16h+d] = sum_e vacc[n][h][e] * Wv[e][16h+d]
// smem: Wv (64KB) + 8 padded fp32 rows (33.8KB) = ~98KB -> 2 blocks/SM (16 warps).
// One warp per row; lane: h = lane>>2, cols 16h + 4*(lane&3)..+3.
#define VPAD 132
#define VROWS 8
#define VTILES (BS/2/VROWS)   // tiles per half = 2048
__global__ void vfold_kernel(const float* __restrict__ Wv, int n_base) {
    extern __shared__ float smem[];
    float* sWv = smem;                 // 128*128 floats
    float* sV  = smem + EDIM*EDIM;     // VROWS * 8*132 floats
    int tid = threadIdx.x;

    for (int i = tid; i < EDIM*EDIM/4; i += 256)
        ((float4*)sWv)[i] = ((const float4*)Wv)[i];

    int wi   = tid >> 5;
    int lane = tid & 31;
    int hh   = lane >> 2;
    const ulonglong2* sWv2 = (const ulonglong2*)sWv;
    const float* svb = sV + (size_t)wi*(NH*VPAD) + hh*VPAD;
    float4* H4 = (float4*)g_hidden;

    for (int tile = blockIdx.x; tile < VTILES; tile += gridDim.x) {
        int n0 = n_base + tile * VROWS;
        // stage VROWS rows of fp16 vacc -> fp32 smem with head padding
        const uint4* gv = (const uint4*)(g_vaccH + (size_t)n0*NH*EDIM);
        for (int i = tid; i < VROWS*128; i += 256) {   // 128 uint4 per row
            uint4 v = gv[i];
            int hi0 = i * 8;
            int row = hi0 >> 10;
            int rem = hi0 & 1023;
            int h   = rem >> 7;
            int e0  = rem & 127;
            const __half2* hp = (const __half2*)&v;
            float2 f0 = __half22float2(hp[0]);
            float2 f1 = __half22float2(hp[1]);
            float2 f2 = __half22float2(hp[2]);
            float2 f3 = __half22float2(hp[3]);
            float* dst = sV + (size_t)row*(NH*VPAD) + h*VPAD + e0;
            *(float4*)(dst)     = make_float4(f0.x, f0.y, f1.x, f1.y);
            *(float4*)(dst + 4) = make_float4(f2.x, f2.y, f3.x, f3.y);
        }
        __syncthreads();

        u64 acc01 = pack2(0.f,0.f), acc23 = pack2(0.f,0.f);
        #pragma unroll 8
        for (int e = 0; e < EDIM; e++) {
            ulonglong2 wp = sWv2[e*32 + lane];
            float v = svb[e];
            u64 vp = pack2(v, v);
            acc01 = fma2(vp, wp.x, acc01);
            acc23 = fma2(vp, wp.y, acc23);
        }
        float4 o;
        unpack2(o.x, o.y, acc01);
        unpack2(o.z, o.w, acc23);
        H4[(size_t)(n0 + wi)*32 + lane] = o;
        __syncthreads();
    }
}

// ============ launcher ============
extern "C" void kernel_launch(void* const* d_in, const int* in_sizes, int n_in,
                              void* d_out, int out_size)
{
    const float* xc_off  = (const float*)d_in[0];
    const float* zc_off  = (const float*)d_in[2];
    const float* zc_on   = (const float*)d_in[3];
    const float* latents = (const float*)d_in[4];
    const float* fake    = (const float*)d_in[5];
    const float* Wq      = (const float*)d_in[6];
    const float* Wk      = (const float*)d_in[7];
    const float* Wv      = (const float*)d_in[8];
    const float* Wo      = (const float*)d_in[9];
    const int*   ignore  = (const int*)d_in[10];
    float* out = (float*)d_out;

    size_t smemG = (size_t)(EDIM*EDIM + 64*EDIM) * sizeof(float);          // 96KB
    size_t smemQ = (size_t)(EDIM*EDIM + 2*QTILE*EDIM) * sizeof(float);     // 96KB
    size_t smemV = (size_t)(EDIM*EDIM + VROWS*NH*VPAD) * sizeof(float);    // ~98KB
    cudaFuncSetAttribute(gemm_kernel,   cudaFuncAttributeMaxDynamicSharedMemorySize, (int)smemG);
    cudaFuncSetAttribute(qaproj_kernel, cudaFuncAttributeMaxDynamicSharedMemorySize, (int)smemQ);
    cudaFuncSetAttribute(vfold_kernel,  cudaFuncAttributeMaxDynamicSharedMemorySize, (int)smemV);

    float *pH;
    int *pCnt;
    cudaGetSymbolAddress((void**)&pH,   g_hidden);
    cudaGetSymbolAddress((void**)&pCnt, g_bcount);

    cudaMemsetAsync(pCnt, 0, BS*sizeof(int));
    qaproj_kernel        <<<SDIM/QTILE, 256, smemQ>>>(latents, Wq, Wk);
    scatter_direct_kernel<<<(BU + 255)/256, 256>>>(xc_off);

    const int HALF = BS/2;
    attn_kernel <<<HALF*32/128, 128>>>(zc_off, zc_on, fake, ignore, 0);
    vfold_kernel<<<296, 256, smemV>>>(Wv, 0);
    attn_kernel <<<HALF*32/128, 128>>>(zc_off, zc_on, fake, ignore, HALF);
    vfold_kernel<<<296, 256, smemV>>>(Wv, HALF);

    gemm_kernel<<<296, 256, smemG>>>(pH, Wo, out, 1.0f, BS);
}